// round 1
// baseline (speedup 1.0000x reference)
#include <cuda_runtime.h>
#include <cstddef>

#define FULL 0xFFFFFFFFu

// dot of a 16-float smem row (16B-aligned) with a 16-float register vector
__device__ __forceinline__ float dot16(const float* __restrict__ w, const float* v) {
    const float4* w4 = (const float4*)w;
    float acc = 0.0f;
#pragma unroll
    for (int q = 0; q < 4; q++) {
        float4 a = w4[q];
        acc = fmaf(a.x, v[4*q+0], acc);
        acc = fmaf(a.y, v[4*q+1], acc);
        acc = fmaf(a.z, v[4*q+2], acc);
        acc = fmaf(a.w, v[4*q+3], acc);
    }
    return acc;
}

__global__ __launch_bounds__(128) void gvae_kernel(
    const float* __restrict__ adj,       // [B,4,13,13]
    const float* __restrict__ init_w,    // [13,16]
    const float* __restrict__ eps_p,     // [4]
    const float* __restrict__ w0g,       // [4,16,16]
    const float* __restrict__ b0g,       // [4,16]
    const float* __restrict__ w1g,       // [4,16,16]
    const float* __restrict__ b1g,       // [4,16]
    const float* __restrict__ big, const float* __restrict__ bib,
    const float* __restrict__ bim, const float* __restrict__ biv,   // [4,13] each
    const float* __restrict__ bog, const float* __restrict__ bob,
    const float* __restrict__ bom, const float* __restrict__ bov,   // [4,13] each
    const float* __restrict__ fc1w, const float* __restrict__ fc1b, // [16,16],[16]
    const float* __restrict__ fc2w, const float* __restrict__ fc2b, // [16,16],[16]
    const float* __restrict__ dwg,       // [4,16,16]
    const float* __restrict__ dbg,       // [4,16]
    float* __restrict__ out, int B)
{
    // ---------------- shared parameter cache ----------------
    __shared__ __align__(16) float sWi[208];            // init_weight [13][16]
    __shared__ __align__(16) float sW0[1024];           // mlp_w0 [4][16][16]
    __shared__ __align__(16) float sW1[1024];
    __shared__ __align__(16) float sDW[1024];           // dec_w
    __shared__ __align__(16) float sF1[256], sF2[256];
    __shared__ float sB0[64], sB1[64], sDB[64];
    __shared__ float sF1b[16], sF2b[16];
    __shared__ float sSin[52], sTin[52], sSout[52], sTout[52];  // folded BN [4][13]
    __shared__ float sEps[4];
    __shared__ __align__(16) float scr[4 * 1352];       // per-warp scratch (2 graphs)

    const int tid = threadIdx.x;

    for (int t = tid; t < 208;  t += 128) sWi[t] = init_w[t];
    for (int t = tid; t < 1024; t += 128) { sW0[t] = w0g[t]; sW1[t] = w1g[t]; sDW[t] = dwg[t]; }
    for (int t = tid; t < 64;   t += 128) { sB0[t] = b0g[t]; sB1[t] = b1g[t]; sDB[t] = dbg[t]; }
    for (int t = tid; t < 256;  t += 128) { sF1[t] = fc1w[t]; sF2[t] = fc2w[t]; }
    if (tid < 16) { sF1b[tid] = fc1b[tid]; sF2b[tid] = fc2b[tid]; }
    if (tid < 4)  sEps[tid] = 1.0f + eps_p[tid];
    for (int t = tid; t < 52; t += 128) {
        float si = big[t] * rsqrtf(biv[t] + 1e-5f);
        sSin[t]  = si; sTin[t]  = bib[t] - bim[t] * si;
        float so = bog[t] * rsqrtf(bov[t] + 1e-5f);
        sSout[t] = so; sTout[t] = bob[t] - bom[t] * so;
    }
    __syncthreads();

    // ---------------- per-warp / per-lane identity ----------------
    const int w    = tid >> 5;
    const int lane = tid & 31;
    const int sub  = lane >> 4;      // which of the 2 graphs in this warp
    const int n    = lane & 15;      // node index; active if n < 13
    const int nn   = (n < 13) ? n : 12;   // clamped for in-bounds addressing
    const long b0  = (long)blockIdx.x * 8 + (long)w * 2;
    if (b0 >= B) return;

    const size_t muOff = (size_t)B * 676;
    const size_t lvOff = muOff + (size_t)B * 208;
    float* scw = scr + w * 1352;

    // ---------------- stage adj (coalesced) then to registers ----------------
    {
        const float4* g  = (const float4*)(adj + (size_t)b0 * 676);
        float4*       s4 = (float4*)scw;
        for (int t = lane; t < 338; t += 32) s4[t] = g[t];
    }
    __syncwarp();
    float aj[4][13];   // adjacency rows for this (graph, node): aj[channel][m]
#pragma unroll
    for (int i = 0; i < 4; i++)
#pragma unroll
        for (int m = 0; m < 13; m++)
            aj[i][m] = scw[sub * 676 + i * 169 + nn * 13 + m];
    __syncwarp();

    // ---------------- x = einsum('binm,md->bnd') ----------------
    float x[16];
#pragma unroll
    for (int d = 0; d < 16; d++) x[d] = 0.0f;
#pragma unroll
    for (int m = 0; m < 13; m++) {
        float a = aj[0][m] + aj[1][m] + aj[2][m] + aj[3][m];
        const float4* wv = (const float4*)(sWi + m * 16);
#pragma unroll
        for (int q = 0; q < 4; q++) {
            float4 wq = wv[q];
            x[q*4+0] = fmaf(a, wq.x, x[q*4+0]);
            x[q*4+1] = fmaf(a, wq.y, x[q*4+1]);
            x[q*4+2] = fmaf(a, wq.z, x[q*4+2]);
            x[q*4+3] = fmaf(a, wq.w, x[q*4+3]);
        }
    }

    // ---------------- 4 GIN layers ----------------
    for (int l = 0; l < 4; l++) {
        const float ep = sEps[l];
        float agg[16];
#pragma unroll
        for (int d = 0; d < 16; d++) agg[d] = ep * x[d];
        // neighbor[n][d] = sum_m adj[d>>2][n][m] * x[m][d]  (x[m] via shuffle)
#pragma unroll
        for (int m = 0; m < 13; m++) {
#pragma unroll
            for (int d = 0; d < 16; d++) {
                float v = __shfl_sync(FULL, x[d], m, 16);
                agg[d] = fmaf(aj[d >> 2][m], v, agg[d]);
            }
        }
        const float sin_  = sSin[l*13 + nn],  tin_  = sTin[l*13 + nn];
        const float sout_ = sSout[l*13 + nn], tout_ = sTout[l*13 + nn];
        const float* W0l = sW0 + l * 256;
        const float* W1l = sW1 + l * 256;
        float h[16];
#pragma unroll
        for (int j = 0; j < 16; j++) {
            float acc = sB0[l*16 + j] + dot16(W0l + j*16, agg);
            float v = fmaf(sin_, acc, tin_);
            h[j] = fmaxf(v, 0.01f * v);          // leaky relu
        }
#pragma unroll
        for (int j = 0; j < 16; j++) {
            float acc = sB1[l*16 + j] + dot16(W1l + j*16, h);
            float v = fmaf(sout_, acc, tout_);
            x[j] = fmaxf(v, 0.01f * v);
        }
    }

    // ---------------- fc1 -> mu (=z), fc2 -> logvar ----------------
    float z[16];
#pragma unroll
    for (int j = 0; j < 16; j++) z[j] = sF1b[j] + dot16(sF1 + j*16, x);
    if (n < 13) {
        float4* o = (float4*)(out + muOff + ((size_t)(b0 + sub) * 13 + n) * 16);
#pragma unroll
        for (int q = 0; q < 4; q++) {
            float4 v; v.x = z[q*4+0]; v.y = z[q*4+1]; v.z = z[q*4+2]; v.w = z[q*4+3];
            o[q] = v;
        }
        float4* o2 = (float4*)(out + lvOff + ((size_t)(b0 + sub) * 13 + n) * 16);
#pragma unroll
        for (int q = 0; q < 4; q++) {
            float4 v;
            v.x = sF2b[q*4+0] + dot16(sF2 + (q*4+0)*16, x);
            v.y = sF2b[q*4+1] + dot16(sF2 + (q*4+1)*16, x);
            v.z = sF2b[q*4+2] + dot16(sF2 + (q*4+2)*16, x);
            v.w = sF2b[q*4+3] + dot16(sF2 + (q*4+3)*16, x);
            o2[q] = v;
        }
    }

    // ---------------- decoder: per channel k, recon = relu(T T^T) ----------------
    for (int k = 0; k < 4; k++) {
        const float* DWk = sDW + k * 256;
        float tp[16];
#pragma unroll
        for (int d = 0; d < 16; d++)
            tp[d] = sDB[k*16 + d] + dot16(DWk + d*16, z);

        float r[13];
#pragma unroll
        for (int m = 0; m < 13; m++) {
            float acc = 0.0f;
#pragma unroll
            for (int d = 0; d < 16; d++) {
                float v = __shfl_sync(FULL, tp[d], m, 16);
                acc = fmaf(tp[d], v, acc);
            }
            r[m] = fmaxf(acc, 0.0f);
        }
        if (n < 13) {
#pragma unroll
            for (int m = 0; m < 13; m++) scw[sub * 169 + n * 13 + m] = r[m];
        }
        __syncwarp();
        for (int t = lane; t < 338; t += 32) {
            int s2 = (t >= 169) ? 1 : 0;
            int rr = t - 169 * s2;
            out[((size_t)(b0 + s2) * 4 + k) * 169 + rr] = scw[t];
        }
        __syncwarp();
    }
}

extern "C" void kernel_launch(void* const* d_in, const int* in_sizes, int n_in,
                              void* d_out, int out_size) {
    const float* adj   = (const float*)d_in[0];
    const float* iw    = (const float*)d_in[1];
    const float* eps   = (const float*)d_in[2];
    const float* w0    = (const float*)d_in[3];
    const float* b0    = (const float*)d_in[4];
    const float* w1    = (const float*)d_in[5];
    const float* b1    = (const float*)d_in[6];
    const float* big   = (const float*)d_in[7];
    const float* bib   = (const float*)d_in[8];
    const float* bim   = (const float*)d_in[9];
    const float* biv   = (const float*)d_in[10];
    const float* bog   = (const float*)d_in[11];
    const float* bob   = (const float*)d_in[12];
    const float* bom   = (const float*)d_in[13];
    const float* bov   = (const float*)d_in[14];
    const float* fc1w  = (const float*)d_in[15];
    const float* fc1b  = (const float*)d_in[16];
    const float* fc2w  = (const float*)d_in[17];
    const float* fc2b  = (const float*)d_in[18];
    const float* dw    = (const float*)d_in[19];
    const float* db    = (const float*)d_in[20];
    float* out = (float*)d_out;

    int B = in_sizes[0] / 676;           // adj elements / (4*13*13)
    int grid = (B + 7) / 8;              // 8 graphs per 128-thread block (2/warp)
    gvae_kernel<<<grid, 128>>>(adj, iw, eps, w0, b0, w1, b1,
                               big, bib, bim, biv, bog, bob, bom, bov,
                               fc1w, fc1b, fc2w, fc2b, dw, db, out, B);
}

// round 3
// speedup vs baseline: 1.0548x; 1.0548x over previous
#include <cuda_runtime.h>
#include <cstddef>

typedef unsigned long long u64;
#define FULL 0xFFFFFFFFu

// ---- packed f32x2 primitives (FFMA2 path, PTX-only per SASS_QUICKREF) ----
__device__ __forceinline__ u64 pk(float lo, float hi) {
    u64 r; asm("mov.b64 %0,{%1,%2};" : "=l"(r) : "f"(lo), "f"(hi)); return r;
}
__device__ __forceinline__ void upk(u64 p, float& a, float& b) {
    asm("mov.b64 {%0,%1},%2;" : "=f"(a), "=f"(b) : "l"(p));
}
__device__ __forceinline__ u64 fma2(u64 a, u64 b, u64 c) {
    u64 d; asm("fma.rn.f32x2 %0,%1,%2,%3;" : "=l"(d) : "l"(a), "l"(b), "l"(c)); return d;
}
__device__ __forceinline__ u64 mul2(u64 a, u64 b) {
    u64 d; asm("mul.rn.f32x2 %0,%1,%2;" : "=l"(d) : "l"(a), "l"(b)); return d;
}
__device__ __forceinline__ u64 add2(u64 a, u64 b) {
    u64 d; asm("add.rn.f32x2 %0,%1,%2;" : "=l"(d) : "l"(a), "l"(b)); return d;
}

// dot of a 16-float smem row (16B aligned) with a packed 8xf32x2 register vector
__device__ __forceinline__ float dot16p(const float* __restrict__ w, const u64* v) {
    const ulonglong2* w2 = (const ulonglong2*)w;
    ulonglong2 p0 = w2[0], p1 = w2[1], p2 = w2[2], p3 = w2[3];
    u64 a0 = mul2(p0.x, v[0]);
    u64 a1 = mul2(p0.y, v[1]);
    a0 = fma2(p1.x, v[2], a0);
    a1 = fma2(p1.y, v[3], a1);
    a0 = fma2(p2.x, v[4], a0);
    a1 = fma2(p2.y, v[5], a1);
    a0 = fma2(p3.x, v[6], a0);
    a1 = fma2(p3.y, v[7], a1);
    a0 = add2(a0, a1);
    float x, y; upk(a0, x, y);
    return x + y;
}

__global__ __launch_bounds__(128) void gvae_kernel(
    const float* __restrict__ adj,       // [B,4,13,13]
    const float* __restrict__ init_w,    // [13,16]
    const float* __restrict__ eps_p,     // [4]
    const float* __restrict__ w0g, const float* __restrict__ b0g,
    const float* __restrict__ w1g, const float* __restrict__ b1g,
    const float* __restrict__ big, const float* __restrict__ bib,
    const float* __restrict__ bim, const float* __restrict__ biv,
    const float* __restrict__ bog, const float* __restrict__ bob,
    const float* __restrict__ bom, const float* __restrict__ bov,
    const float* __restrict__ fc1w, const float* __restrict__ fc1b,
    const float* __restrict__ fc2w, const float* __restrict__ fc2b,
    const float* __restrict__ dwg, const float* __restrict__ dbg,
    float* __restrict__ out, int B)
{
    __shared__ __align__(16) float sWi[208];
    __shared__ __align__(16) float sW0[1024], sW1[1024], sDW[1024];
    __shared__ __align__(16) float sF1[256], sF2[256];
    __shared__ float sB0[64], sB1[64], sDB[64], sF1b[16], sF2b[16];
    __shared__ float sSin[52], sTin[52], sSout[52], sTout[52];
    __shared__ float sEps[4];
    __shared__ __align__(16) float scr[4 * 1352];

    const int tid = threadIdx.x;
    for (int t = tid; t < 208;  t += 128) sWi[t] = init_w[t];
    for (int t = tid; t < 1024; t += 128) { sW0[t] = w0g[t]; sW1[t] = w1g[t]; sDW[t] = dwg[t]; }
    for (int t = tid; t < 64;   t += 128) { sB0[t] = b0g[t]; sB1[t] = b1g[t]; sDB[t] = dbg[t]; }
    for (int t = tid; t < 256;  t += 128) { sF1[t] = fc1w[t]; sF2[t] = fc2w[t]; }
    if (tid < 16) { sF1b[tid] = fc1b[tid]; sF2b[tid] = fc2b[tid]; }
    if (tid < 4)  sEps[tid] = 1.0f + eps_p[tid];
    for (int t = tid; t < 52; t += 128) {
        float si = big[t] * rsqrtf(biv[t] + 1e-5f);
        sSin[t]  = si; sTin[t]  = bib[t] - bim[t] * si;
        float so = bog[t] * rsqrtf(bov[t] + 1e-5f);
        sSout[t] = so; sTout[t] = bob[t] - bom[t] * so;
    }
    __syncthreads();

    const int w    = tid >> 5;
    const int lane = tid & 31;
    const int sub  = lane >> 4;
    const int n    = lane & 15;
    const int nn   = (n < 13) ? n : 12;
    const long b0  = (long)blockIdx.x * 8 + (long)w * 2;
    if (b0 >= B) return;

    const size_t muOff = (size_t)B * 676;
    const size_t lvOff = muOff + (size_t)B * 208;
    float* scw = scr + w * 1352;
    float* xb  = scw;            // broadcast region [2][13][16]
    float* rb  = scw + 416;      // decoder row staging [2][169]

    // ---- stage adj coalesced, scatter to registers ----
    {
        const float4* g  = (const float4*)(adj + (size_t)b0 * 676);
        float4*       s4 = (float4*)scw;
        for (int t = lane; t < 338; t += 32) s4[t] = g[t];
    }
    __syncwarp();
    float aj[4][13];
#pragma unroll
    for (int i = 0; i < 4; i++)
#pragma unroll
        for (int m = 0; m < 13; m++)
            aj[i][m] = scw[sub * 676 + i * 169 + nn * 13 + m];
    __syncwarp();

    // ---- x = einsum('binm,md->bnd'), packed ----
    u64 xp[8];
    {
        float a0 = aj[0][0] + aj[1][0] + aj[2][0] + aj[3][0];
        u64 aa = pk(a0, a0);
        const ulonglong2* wv = (const ulonglong2*)(sWi);
#pragma unroll
        for (int q = 0; q < 4; q++) {
            ulonglong2 wq = wv[q];
            xp[2*q+0] = mul2(aa, wq.x);
            xp[2*q+1] = mul2(aa, wq.y);
        }
#pragma unroll
        for (int m = 1; m < 13; m++) {
            float a = aj[0][m] + aj[1][m] + aj[2][m] + aj[3][m];
            u64 am = pk(a, a);
            const ulonglong2* wm = (const ulonglong2*)(sWi + m * 16);
#pragma unroll
            for (int q = 0; q < 4; q++) {
                ulonglong2 wq = wm[q];
                xp[2*q+0] = fma2(am, wq.x, xp[2*q+0]);
                xp[2*q+1] = fma2(am, wq.y, xp[2*q+1]);
            }
        }
    }

    // ---- 4 GIN layers ----
    for (int l = 0; l < 4; l++) {
        // publish packed x to warp smem
        if (n < 13) {
            ulonglong2* xv = (ulonglong2*)(xb + (sub * 13 + nn) * 16);
#pragma unroll
            for (int q = 0; q < 4; q++) {
                ulonglong2 v; v.x = xp[2*q]; v.y = xp[2*q+1];
                xv[q] = v;
            }
        }
        __syncwarp();

        const float ep = sEps[l];
        const u64 ep2 = pk(ep, ep);
        u64 agg[8];
#pragma unroll
        for (int q = 0; q < 8; q++) agg[q] = mul2(ep2, xp[q]);
#pragma unroll
        for (int m = 0; m < 13; m++) {
            const ulonglong2* xv = (const ulonglong2*)(xb + (sub * 13 + m) * 16);
            ulonglong2 v0 = xv[0], v1 = xv[1], v2 = xv[2], v3 = xv[3];
            u64 a0 = pk(aj[0][m], aj[0][m]);
            u64 a1 = pk(aj[1][m], aj[1][m]);
            u64 a2 = pk(aj[2][m], aj[2][m]);
            u64 a3 = pk(aj[3][m], aj[3][m]);
            agg[0] = fma2(a0, v0.x, agg[0]); agg[1] = fma2(a0, v0.y, agg[1]);
            agg[2] = fma2(a1, v1.x, agg[2]); agg[3] = fma2(a1, v1.y, agg[3]);
            agg[4] = fma2(a2, v2.x, agg[4]); agg[5] = fma2(a2, v2.y, agg[5]);
            agg[6] = fma2(a3, v3.x, agg[6]); agg[7] = fma2(a3, v3.y, agg[7]);
        }
        __syncwarp();   // xb free for next writer

        const float sin_  = sSin[l*13 + nn],  tin_  = sTin[l*13 + nn];
        const float sout_ = sSout[l*13 + nn], tout_ = sTout[l*13 + nn];
        u64 hp[8];
#pragma unroll
        for (int q = 0; q < 8; q++) {
            float acc0 = sB0[l*16 + 2*q]     + dot16p(sW0 + l*256 + (2*q)*16,   agg);
            float acc1 = sB0[l*16 + 2*q + 1] + dot16p(sW0 + l*256 + (2*q+1)*16, agg);
            float v0 = fmaf(sin_, acc0, tin_);
            float v1 = fmaf(sin_, acc1, tin_);
            hp[q] = pk(fmaxf(v0, 0.01f * v0), fmaxf(v1, 0.01f * v1));
        }
#pragma unroll
        for (int q = 0; q < 8; q++) {
            float acc0 = sB1[l*16 + 2*q]     + dot16p(sW1 + l*256 + (2*q)*16,   hp);
            float acc1 = sB1[l*16 + 2*q + 1] + dot16p(sW1 + l*256 + (2*q+1)*16, hp);
            float v0 = fmaf(sout_, acc0, tout_);
            float v1 = fmaf(sout_, acc1, tout_);
            xp[q] = pk(fmaxf(v0, 0.01f * v0), fmaxf(v1, 0.01f * v1));
        }
    }

    // ---- fc1 -> mu (=z), fc2 -> logvar ----
    u64 zp[8];
#pragma unroll
    for (int q = 0; q < 8; q++) {
        float z0 = sF1b[2*q]     + dot16p(sF1 + (2*q)*16,   xp);
        float z1 = sF1b[2*q + 1] + dot16p(sF1 + (2*q+1)*16, xp);
        zp[q] = pk(z0, z1);
    }
    if (n < 13) {
        ulonglong2* o = (ulonglong2*)(out + muOff + ((size_t)(b0 + sub) * 13 + n) * 16);
#pragma unroll
        for (int q = 0; q < 4; q++) {
            ulonglong2 v; v.x = zp[2*q]; v.y = zp[2*q+1];
            o[q] = v;
        }
        ulonglong2* o2 = (ulonglong2*)(out + lvOff + ((size_t)(b0 + sub) * 13 + n) * 16);
#pragma unroll
        for (int q = 0; q < 4; q++) {
            ulonglong2 v;
            v.x = pk(sF2b[4*q]   + dot16p(sF2 + (4*q)*16,   xp),
                     sF2b[4*q+1] + dot16p(sF2 + (4*q+1)*16, xp));
            v.y = pk(sF2b[4*q+2] + dot16p(sF2 + (4*q+2)*16, xp),
                     sF2b[4*q+3] + dot16p(sF2 + (4*q+3)*16, xp));
            o2[q] = v;
        }
    }

    // ---- decoder: per channel k, recon = relu(T T^T) ----
    for (int k = 0; k < 4; k++) {
        u64 tp2[8];
#pragma unroll
        for (int q = 0; q < 8; q++) {
            float t0 = sDB[k*16 + 2*q]     + dot16p(sDW + k*256 + (2*q)*16,   zp);
            float t1 = sDB[k*16 + 2*q + 1] + dot16p(sDW + k*256 + (2*q+1)*16, zp);
            tp2[q] = pk(t0, t1);
        }

        __syncwarp();   // prior readers of xb done
        if (n < 13) {
            ulonglong2* tv = (ulonglong2*)(xb + (sub * 13 + nn) * 16);
#pragma unroll
            for (int q = 0; q < 4; q++) {
                ulonglong2 v; v.x = tp2[2*q]; v.y = tp2[2*q+1];
                tv[q] = v;
            }
        }
        __syncwarp();

        float r[13];
#pragma unroll
        for (int m = 0; m < 13; m++) {
            const ulonglong2* tv = (const ulonglong2*)(xb + (sub * 13 + m) * 16);
            ulonglong2 v0 = tv[0], v1 = tv[1], v2 = tv[2], v3 = tv[3];
            u64 s0 = mul2(tp2[0], v0.x);
            u64 s1 = mul2(tp2[1], v0.y);
            s0 = fma2(tp2[2], v1.x, s0);
            s1 = fma2(tp2[3], v1.y, s1);
            s0 = fma2(tp2[4], v2.x, s0);
            s1 = fma2(tp2[5], v2.y, s1);
            s0 = fma2(tp2[6], v3.x, s0);
            s1 = fma2(tp2[7], v3.y, s1);
            s0 = add2(s0, s1);
            float x0, x1; upk(s0, x0, x1);
            r[m] = fmaxf(x0 + x1, 0.0f);
        }
        if (n < 13) {
#pragma unroll
            for (int m = 0; m < 13; m++) rb[sub * 169 + nn * 13 + m] = r[m];
        }
        __syncwarp();
        for (int t = lane; t < 338; t += 32) {
            int s2 = (t >= 169) ? 1 : 0;
            int rr = t - 169 * s2;
            out[((size_t)(b0 + s2) * 4 + k) * 169 + rr] = rb[t];
        }
        __syncwarp();
    }
}

extern "C" void kernel_launch(void* const* d_in, const int* in_sizes, int n_in,
                              void* d_out, int out_size) {
    const float* adj = (const float*)d_in[0];
    float* out = (float*)d_out;
    int B = in_sizes[0] / 676;
    int grid = (B + 7) / 8;
    gvae_kernel<<<grid, 128>>>(adj,
        (const float*)d_in[1],  (const float*)d_in[2],
        (const float*)d_in[3],  (const float*)d_in[4],
        (const float*)d_in[5],  (const float*)d_in[6],
        (const float*)d_in[7],  (const float*)d_in[8],
        (const float*)d_in[9],  (const float*)d_in[10],
        (const float*)d_in[11], (const float*)d_in[12],
        (const float*)d_in[13], (const float*)d_in[14],
        (const float*)d_in[15], (const float*)d_in[16],
        (const float*)d_in[17], (const float*)d_in[18],
        (const float*)d_in[19], (const float*)d_in[20],
        out, B);
}

// round 4
// speedup vs baseline: 1.0613x; 1.0062x over previous
#include <cuda_runtime.h>
#include <cstddef>

typedef unsigned long long u64;

// ---------------- constant-memory parameter bank (uniform LDCU path) ----------
__constant__ float cWi[208];                 // init_weight [13][16]
__constant__ float cW0[1024], cB0[64];       // mlp_w0 [4][16][16], b0 [4][16]
__constant__ float cW1[1024], cB1[64];
__constant__ float cF1[256],  cF1b[16];
__constant__ float cF2[256],  cF2b[16];
__constant__ float cDW[1024], cDB[64];
__constant__ float cEps[4];

// ---- packed f32x2 primitives (FFMA2 path, PTX-only per SASS_QUICKREF) ----
__device__ __forceinline__ u64 pk(float lo, float hi) {
    u64 r; asm("mov.b64 %0,{%1,%2};" : "=l"(r) : "f"(lo), "f"(hi)); return r;
}
__device__ __forceinline__ void upk(u64 p, float& a, float& b) {
    asm("mov.b64 {%0,%1},%2;" : "=f"(a), "=f"(b) : "l"(p));
}
__device__ __forceinline__ u64 fma2(u64 a, u64 b, u64 c) {
    u64 d; asm("fma.rn.f32x2 %0,%1,%2,%3;" : "=l"(d) : "l"(a), "l"(b), "l"(c)); return d;
}
__device__ __forceinline__ u64 mul2(u64 a, u64 b) {
    u64 d; asm("mul.rn.f32x2 %0,%1,%2;" : "=l"(d) : "l"(a), "l"(b)); return d;
}
__device__ __forceinline__ u64 add2(u64 a, u64 b) {
    u64 d; asm("add.rn.f32x2 %0,%1,%2;" : "=l"(d) : "l"(a), "l"(b)); return d;
}

// dot of a 16-float constant row with a packed 8xf32x2 register vector
__device__ __forceinline__ float dot16c(const float* __restrict__ w, const u64* v) {
    u64 a0 = mul2(pk(w[0],  w[1]),  v[0]);
    u64 a1 = mul2(pk(w[2],  w[3]),  v[1]);
    a0 = fma2(pk(w[4],  w[5]),  v[2], a0);
    a1 = fma2(pk(w[6],  w[7]),  v[3], a1);
    a0 = fma2(pk(w[8],  w[9]),  v[4], a0);
    a1 = fma2(pk(w[10], w[11]), v[5], a1);
    a0 = fma2(pk(w[12], w[13]), v[6], a0);
    a1 = fma2(pk(w[14], w[15]), v[7], a1);
    a0 = add2(a0, a1);
    float x, y; upk(a0, x, y);
    return x + y;
}

__global__ __launch_bounds__(128, 4) void gvae_kernel(
    const float* __restrict__ adj,       // [B,4,13,13]
    const float* __restrict__ big, const float* __restrict__ bib,
    const float* __restrict__ bim, const float* __restrict__ biv,   // [4,13]
    const float* __restrict__ bog, const float* __restrict__ bob,
    const float* __restrict__ bom, const float* __restrict__ bov,   // [4,13]
    float* __restrict__ out, int B)
{
    __shared__ float sSin[52], sTin[52], sSout[52], sTout[52];  // folded BN [4][13]
    __shared__ __align__(16) float scr[4 * 1352];               // per-warp scratch

    const int tid = threadIdx.x;
    for (int t = tid; t < 52; t += 128) {
        float si = big[t] * rsqrtf(biv[t] + 1e-5f);
        sSin[t]  = si; sTin[t]  = bib[t] - bim[t] * si;
        float so = bog[t] * rsqrtf(bov[t] + 1e-5f);
        sSout[t] = so; sTout[t] = bob[t] - bom[t] * so;
    }
    __syncthreads();

    const int w    = tid >> 5;
    const int lane = tid & 31;
    const int sub  = lane >> 4;
    const int n    = lane & 15;
    const int nn   = (n < 13) ? n : 12;
    const long b0  = (long)blockIdx.x * 8 + (long)w * 2;
    if (b0 >= B) return;

    const size_t muOff = (size_t)B * 676;
    const size_t lvOff = muOff + (size_t)B * 208;
    float* scw = scr + w * 1352;
    float* xb  = scw;            // broadcast region [2][13][16]
    float* rb  = scw + 416;      // decoder row staging [2][169]

    // ---- stage adj coalesced, scatter to registers ----
    {
        const float4* g  = (const float4*)(adj + (size_t)b0 * 676);
        float4*       s4 = (float4*)scw;
        for (int t = lane; t < 338; t += 32) s4[t] = g[t];
    }
    __syncwarp();
    float aj[4][13];
#pragma unroll
    for (int i = 0; i < 4; i++)
#pragma unroll
        for (int m = 0; m < 13; m++)
            aj[i][m] = scw[sub * 676 + i * 169 + nn * 13 + m];
    __syncwarp();

    // ---- x = einsum('binm,md->bnd'), packed, weights from constant ----
    u64 xp[8];
    {
        float a0 = aj[0][0] + aj[1][0] + aj[2][0] + aj[3][0];
        u64 aa = pk(a0, a0);
#pragma unroll
        for (int q = 0; q < 8; q++)
            xp[q] = mul2(aa, pk(cWi[2*q], cWi[2*q+1]));
#pragma unroll
        for (int m = 1; m < 13; m++) {
            float a = aj[0][m] + aj[1][m] + aj[2][m] + aj[3][m];
            u64 am = pk(a, a);
#pragma unroll
            for (int q = 0; q < 8; q++)
                xp[q] = fma2(am, pk(cWi[m*16 + 2*q], cWi[m*16 + 2*q+1]), xp[q]);
        }
    }

    // ---- 4 GIN layers ----
    for (int l = 0; l < 4; l++) {
        // publish packed x to warp smem
        if (n < 13) {
            ulonglong2* xv = (ulonglong2*)(xb + (sub * 13 + nn) * 16);
#pragma unroll
            for (int q = 0; q < 4; q++) {
                ulonglong2 v; v.x = xp[2*q]; v.y = xp[2*q+1];
                xv[q] = v;
            }
        }
        __syncwarp();

        const float ep = 1.0f + cEps[l];
        const u64 ep2 = pk(ep, ep);
        u64 agg[8];
#pragma unroll
        for (int q = 0; q < 8; q++) agg[q] = mul2(ep2, xp[q]);
#pragma unroll
        for (int m = 0; m < 13; m++) {
            const ulonglong2* xv = (const ulonglong2*)(xb + (sub * 13 + m) * 16);
            ulonglong2 v0 = xv[0], v1 = xv[1], v2 = xv[2], v3 = xv[3];
            u64 a0 = pk(aj[0][m], aj[0][m]);
            u64 a1 = pk(aj[1][m], aj[1][m]);
            u64 a2 = pk(aj[2][m], aj[2][m]);
            u64 a3 = pk(aj[3][m], aj[3][m]);
            agg[0] = fma2(a0, v0.x, agg[0]); agg[1] = fma2(a0, v0.y, agg[1]);
            agg[2] = fma2(a1, v1.x, agg[2]); agg[3] = fma2(a1, v1.y, agg[3]);
            agg[4] = fma2(a2, v2.x, agg[4]); agg[5] = fma2(a2, v2.y, agg[5]);
            agg[6] = fma2(a3, v3.x, agg[6]); agg[7] = fma2(a3, v3.y, agg[7]);
        }
        __syncwarp();   // xb free for next writer

        const float sin_  = sSin[l*13 + nn],  tin_  = sTin[l*13 + nn];
        const float sout_ = sSout[l*13 + nn], tout_ = sTout[l*13 + nn];
        u64 hp[8];
#pragma unroll
        for (int q = 0; q < 8; q++) {
            float acc0 = cB0[l*16 + 2*q]     + dot16c(cW0 + l*256 + (2*q)*16,   agg);
            float acc1 = cB0[l*16 + 2*q + 1] + dot16c(cW0 + l*256 + (2*q+1)*16, agg);
            float v0 = fmaf(sin_, acc0, tin_);
            float v1 = fmaf(sin_, acc1, tin_);
            hp[q] = pk(fmaxf(v0, 0.01f * v0), fmaxf(v1, 0.01f * v1));
        }
#pragma unroll
        for (int q = 0; q < 8; q++) {
            float acc0 = cB1[l*16 + 2*q]     + dot16c(cW1 + l*256 + (2*q)*16,   hp);
            float acc1 = cB1[l*16 + 2*q + 1] + dot16c(cW1 + l*256 + (2*q+1)*16, hp);
            float v0 = fmaf(sout_, acc0, tout_);
            float v1 = fmaf(sout_, acc1, tout_);
            xp[q] = pk(fmaxf(v0, 0.01f * v0), fmaxf(v1, 0.01f * v1));
        }
    }

    // ---- fc1 -> mu (=z), fc2 -> logvar ----
    u64 zp[8];
#pragma unroll
    for (int q = 0; q < 8; q++) {
        float z0 = cF1b[2*q]     + dot16c(cF1 + (2*q)*16,   xp);
        float z1 = cF1b[2*q + 1] + dot16c(cF1 + (2*q+1)*16, xp);
        zp[q] = pk(z0, z1);
    }
    if (n < 13) {
        ulonglong2* o = (ulonglong2*)(out + muOff + ((size_t)(b0 + sub) * 13 + n) * 16);
#pragma unroll
        for (int q = 0; q < 4; q++) {
            ulonglong2 v; v.x = zp[2*q]; v.y = zp[2*q+1];
            o[q] = v;
        }
        ulonglong2* o2 = (ulonglong2*)(out + lvOff + ((size_t)(b0 + sub) * 13 + n) * 16);
#pragma unroll
        for (int q = 0; q < 4; q++) {
            ulonglong2 v;
            v.x = pk(cF2b[4*q]   + dot16c(cF2 + (4*q)*16,   xp),
                     cF2b[4*q+1] + dot16c(cF2 + (4*q+1)*16, xp));
            v.y = pk(cF2b[4*q+2] + dot16c(cF2 + (4*q+2)*16, xp),
                     cF2b[4*q+3] + dot16c(cF2 + (4*q+3)*16, xp));
            o2[q] = v;
        }
    }

    // ---- decoder: per channel k, recon = relu(T T^T) ----
    for (int k = 0; k < 4; k++) {
        u64 tp2[8];
#pragma unroll
        for (int q = 0; q < 8; q++) {
            float t0 = cDB[k*16 + 2*q]     + dot16c(cDW + k*256 + (2*q)*16,   zp);
            float t1 = cDB[k*16 + 2*q + 1] + dot16c(cDW + k*256 + (2*q+1)*16, zp);
            tp2[q] = pk(t0, t1);
        }

        __syncwarp();   // prior readers of xb done
        if (n < 13) {
            ulonglong2* tv = (ulonglong2*)(xb + (sub * 13 + nn) * 16);
#pragma unroll
            for (int q = 0; q < 4; q++) {
                ulonglong2 v; v.x = tp2[2*q]; v.y = tp2[2*q+1];
                tv[q] = v;
            }
        }
        __syncwarp();

        float r[13];
#pragma unroll
        for (int m = 0; m < 13; m++) {
            const ulonglong2* tv = (const ulonglong2*)(xb + (sub * 13 + m) * 16);
            ulonglong2 v0 = tv[0], v1 = tv[1], v2 = tv[2], v3 = tv[3];
            u64 s0 = mul2(tp2[0], v0.x);
            u64 s1 = mul2(tp2[1], v0.y);
            s0 = fma2(tp2[2], v1.x, s0);
            s1 = fma2(tp2[3], v1.y, s1);
            s0 = fma2(tp2[4], v2.x, s0);
            s1 = fma2(tp2[5], v2.y, s1);
            s0 = fma2(tp2[6], v3.x, s0);
            s1 = fma2(tp2[7], v3.y, s1);
            s0 = add2(s0, s1);
            float x0, x1; upk(s0, x0, x1);
            r[m] = fmaxf(x0 + x1, 0.0f);
        }
        if (n < 13) {
#pragma unroll
            for (int m = 0; m < 13; m++) rb[sub * 169 + nn * 13 + m] = r[m];
        }
        __syncwarp();
        for (int t = lane; t < 338; t += 32) {
            int s2 = (t >= 169) ? 1 : 0;
            int rr = t - 169 * s2;
            out[((size_t)(b0 + s2) * 4 + k) * 169 + rr] = rb[t];
        }
        __syncwarp();
    }
}

extern "C" void kernel_launch(void* const* d_in, const int* in_sizes, int n_in,
                              void* d_out, int out_size) {
    // constant-bank uploads: D2D memcpy nodes, graph-capturable, no allocation
    cudaMemcpyToSymbolAsync(cWi,  d_in[1],  208 * 4, 0, cudaMemcpyDeviceToDevice);
    cudaMemcpyToSymbolAsync(cEps, d_in[2],    4 * 4, 0, cudaMemcpyDeviceToDevice);
    cudaMemcpyToSymbolAsync(cW0,  d_in[3], 1024 * 4, 0, cudaMemcpyDeviceToDevice);
    cudaMemcpyToSymbolAsync(cB0,  d_in[4],   64 * 4, 0, cudaMemcpyDeviceToDevice);
    cudaMemcpyToSymbolAsync(cW1,  d_in[5], 1024 * 4, 0, cudaMemcpyDeviceToDevice);
    cudaMemcpyToSymbolAsync(cB1,  d_in[6],   64 * 4, 0, cudaMemcpyDeviceToDevice);
    cudaMemcpyToSymbolAsync(cF1,  d_in[15], 256 * 4, 0, cudaMemcpyDeviceToDevice);
    cudaMemcpyToSymbolAsync(cF1b, d_in[16],  16 * 4, 0, cudaMemcpyDeviceToDevice);
    cudaMemcpyToSymbolAsync(cF2,  d_in[17], 256 * 4, 0, cudaMemcpyDeviceToDevice);
    cudaMemcpyToSymbolAsync(cF2b, d_in[18],  16 * 4, 0, cudaMemcpyDeviceToDevice);
    cudaMemcpyToSymbolAsync(cDW,  d_in[19],1024 * 4, 0, cudaMemcpyDeviceToDevice);
    cudaMemcpyToSymbolAsync(cDB,  d_in[20],  64 * 4, 0, cudaMemcpyDeviceToDevice);

    const float* adj = (const float*)d_in[0];
    float* out = (float*)d_out;
    int B = in_sizes[0] / 676;
    int grid = (B + 7) / 8;
    gvae_kernel<<<grid, 128>>>(adj,
        (const float*)d_in[7],  (const float*)d_in[8],
        (const float*)d_in[9],  (const float*)d_in[10],
        (const float*)d_in[11], (const float*)d_in[12],
        (const float*)d_in[13], (const float*)d_in[14],
        out, B);
}

// round 6
// speedup vs baseline: 1.1722x; 1.1045x over previous
#include <cuda_runtime.h>
#include <cstddef>

typedef unsigned long long u64;

// ---- low-traffic parameters in constant (uniform port) ----
__constant__ float cWi[208];                 // init_weight [13][16]
__constant__ float cB0[64], cB1[64];
__constant__ float cF1[256], cF1b[16];
__constant__ float cF2[256], cF2b[16];
__constant__ float cDB[64];
__constant__ float cEps[4];

// ---- packed f32x2 primitives ----
__device__ __forceinline__ u64 pk(float lo, float hi) {
    u64 r; asm("mov.b64 %0,{%1,%2};" : "=l"(r) : "f"(lo), "f"(hi)); return r;
}
__device__ __forceinline__ void upk(u64 p, float& a, float& b) {
    asm("mov.b64 {%0,%1},%2;" : "=f"(a), "=f"(b) : "l"(p));
}
__device__ __forceinline__ u64 fma2(u64 a, u64 b, u64 c) {
    u64 d; asm("fma.rn.f32x2 %0,%1,%2,%3;" : "=l"(d) : "l"(a), "l"(b), "l"(c)); return d;
}
__device__ __forceinline__ u64 mul2(u64 a, u64 b) {
    u64 d; asm("mul.rn.f32x2 %0,%1,%2;" : "=l"(d) : "l"(a), "l"(b)); return d;
}
__device__ __forceinline__ u64 add2(u64 a, u64 b) {
    u64 d; asm("add.rn.f32x2 %0,%1,%2;" : "=l"(d) : "l"(a), "l"(b)); return d;
}

// dot: 16-float smem row (16B aligned, LDS.128 path) with packed 8xf32x2 vector
__device__ __forceinline__ float dot16s(const float* __restrict__ w, const u64* v) {
    const ulonglong2* w2 = (const ulonglong2*)w;
    ulonglong2 p0 = w2[0], p1 = w2[1], p2 = w2[2], p3 = w2[3];
    u64 a0 = mul2(p0.x, v[0]);
    u64 a1 = mul2(p0.y, v[1]);
    a0 = fma2(p1.x, v[2], a0);
    a1 = fma2(p1.y, v[3], a1);
    a0 = fma2(p2.x, v[4], a0);
    a1 = fma2(p2.y, v[5], a1);
    a0 = fma2(p3.x, v[6], a0);
    a1 = fma2(p3.y, v[7], a1);
    a0 = add2(a0, a1);
    float x, y; upk(a0, x, y);
    return x + y;
}

// dot: 16-float constant row with packed vector
__device__ __forceinline__ float dot16c(const float* __restrict__ w, const u64* v) {
    u64 a0 = mul2(pk(w[0],  w[1]),  v[0]);
    u64 a1 = mul2(pk(w[2],  w[3]),  v[1]);
    a0 = fma2(pk(w[4],  w[5]),  v[2], a0);
    a1 = fma2(pk(w[6],  w[7]),  v[3], a1);
    a0 = fma2(pk(w[8],  w[9]),  v[4], a0);
    a1 = fma2(pk(w[10], w[11]), v[5], a1);
    a0 = fma2(pk(w[12], w[13]), v[6], a0);
    a1 = fma2(pk(w[14], w[15]), v[7], a1);
    a0 = add2(a0, a1);
    float x, y; upk(a0, x, y);
    return x + y;
}

__global__ __launch_bounds__(128, 5) void gvae_kernel(
    const float* __restrict__ adj,       // [B,4,13,13]
    const float* __restrict__ w0g, const float* __restrict__ w1g,
    const float* __restrict__ dwg,       // [4,16,16] each
    const float* __restrict__ big, const float* __restrict__ bib,
    const float* __restrict__ bim, const float* __restrict__ biv,
    const float* __restrict__ bog, const float* __restrict__ bob,
    const float* __restrict__ bom, const float* __restrict__ bov,
    float* __restrict__ out, int B)
{
    __shared__ __align__(16) float sW0[1024], sW1[1024], sDW[1024];  // 12 KB
    __shared__ float sSin[52], sTin[52], sSout[52], sTout[52];       // folded BN
    __shared__ __align__(16) float scr[4 * 1352];                    // adjT / rb
    __shared__ __align__(16) float xbs[4 * 416];                     // x broadcast

    const int tid = threadIdx.x;
    for (int t = tid; t < 1024; t += 128) { sW0[t] = w0g[t]; sW1[t] = w1g[t]; sDW[t] = dwg[t]; }
    for (int t = tid; t < 52; t += 128) {
        float si = big[t] * rsqrtf(biv[t] + 1e-5f);
        sSin[t]  = si; sTin[t]  = bib[t] - bim[t] * si;
        float so = bog[t] * rsqrtf(bov[t] + 1e-5f);
        sSout[t] = so; sTout[t] = bob[t] - bom[t] * so;
    }
    __syncthreads();

    const int w    = tid >> 5;
    const int lane = tid & 31;
    const int sub  = lane >> 4;            // 2 graphs per warp
    const int n    = lane & 15;            // node id; active if n < 13
    const int nn   = (n < 13) ? n : 12;
    const long b0  = (long)blockIdx.x * 8 + (long)w * 2;
    if (b0 >= B) return;

    const size_t muOff = (size_t)B * 676;
    const size_t lvOff = muOff + (size_t)B * 208;
    float* scw = scr + w * 1352;           // raw adj -> adjT -> (decoder) rb
    float* xb  = xbs + w * 416;            // [2][13][16] broadcast

    // ---- stage raw adj coalesced ----
    {
        const float4* g  = (const float4*)(adj + (size_t)b0 * 676);
        float4*       s4 = (float4*)scw;
        for (int t = lane; t < 338; t += 32) s4[t] = g[t];
    }
    __syncwarp();

    // ---- read this lane's rows (transient regs), compute xp, write adjT ----
    float raw[4][13];
#pragma unroll
    for (int c = 0; c < 4; c++)
#pragma unroll
        for (int m = 0; m < 13; m++)
            raw[c][m] = scw[sub * 676 + c * 169 + nn * 13 + m];

    u64 xp[8];
    {
        float a0 = raw[0][0] + raw[1][0] + raw[2][0] + raw[3][0];
        u64 aa = pk(a0, a0);
#pragma unroll
        for (int q = 0; q < 8; q++)
            xp[q] = mul2(aa, pk(cWi[2*q], cWi[2*q+1]));
#pragma unroll
        for (int m = 1; m < 13; m++) {
            float a = raw[0][m] + raw[1][m] + raw[2][m] + raw[3][m];
            u64 am = pk(a, a);
#pragma unroll
            for (int q = 0; q < 8; q++)
                xp[q] = fma2(am, pk(cWi[m*16 + 2*q], cWi[m*16 + 2*q+1]), xp[q]);
        }
    }
    __syncwarp();          // all raw reads done before adjT overwrites
    if (n < 13) {
        float4* adjT = (float4*)scw;
#pragma unroll
        for (int m = 0; m < 13; m++) {
            float4 v; v.x = raw[0][m]; v.y = raw[1][m]; v.z = raw[2][m]; v.w = raw[3][m];
            adjT[(sub * 13 + nn) * 13 + m] = v;
        }
    }
    __syncwarp();

    // ---- 4 GIN layers ----
    const float4* adjT = (const float4*)scw;
    for (int l = 0; l < 4; l++) {
        if (n < 13) {
            ulonglong2* xv = (ulonglong2*)(xb + (sub * 13 + nn) * 16);
#pragma unroll
            for (int q = 0; q < 4; q++) {
                ulonglong2 v; v.x = xp[2*q]; v.y = xp[2*q+1];
                xv[q] = v;
            }
        }
        __syncwarp();

        const float ep = 1.0f + cEps[l];
        const u64 ep2 = pk(ep, ep);
        u64 agg[8];
#pragma unroll
        for (int q = 0; q < 8; q++) agg[q] = mul2(ep2, xp[q]);
#pragma unroll
        for (int m = 0; m < 13; m++) {
            float4 a4 = adjT[(sub * 13 + nn) * 13 + m];
            const ulonglong2* xv = (const ulonglong2*)(xb + (sub * 13 + m) * 16);
            ulonglong2 v0 = xv[0], v1 = xv[1], v2 = xv[2], v3 = xv[3];
            u64 a0 = pk(a4.x, a4.x);
            u64 a1 = pk(a4.y, a4.y);
            u64 a2 = pk(a4.z, a4.z);
            u64 a3 = pk(a4.w, a4.w);
            agg[0] = fma2(a0, v0.x, agg[0]); agg[1] = fma2(a0, v0.y, agg[1]);
            agg[2] = fma2(a1, v1.x, agg[2]); agg[3] = fma2(a1, v1.y, agg[3]);
            agg[4] = fma2(a2, v2.x, agg[4]); agg[5] = fma2(a2, v2.y, agg[5]);
            agg[6] = fma2(a3, v3.x, agg[6]); agg[7] = fma2(a3, v3.y, agg[7]);
        }
        __syncwarp();      // xb free for next writer

        const float sin_  = sSin[l*13 + nn],  tin_  = sTin[l*13 + nn];
        const float sout_ = sSout[l*13 + nn], tout_ = sTout[l*13 + nn];
        u64 hp[8];
#pragma unroll
        for (int q = 0; q < 8; q++) {
            float acc0 = cB0[l*16 + 2*q]     + dot16s(sW0 + l*256 + (2*q)*16,   agg);
            float acc1 = cB0[l*16 + 2*q + 1] + dot16s(sW0 + l*256 + (2*q+1)*16, agg);
            float v0 = fmaf(sin_, acc0, tin_);
            float v1 = fmaf(sin_, acc1, tin_);
            hp[q] = pk(fmaxf(v0, 0.01f * v0), fmaxf(v1, 0.01f * v1));
        }
#pragma unroll
        for (int q = 0; q < 8; q++) {
            float acc0 = cB1[l*16 + 2*q]     + dot16s(sW1 + l*256 + (2*q)*16,   hp);
            float acc1 = cB1[l*16 + 2*q + 1] + dot16s(sW1 + l*256 + (2*q+1)*16, hp);
            float v0 = fmaf(sout_, acc0, tout_);
            float v1 = fmaf(sout_, acc1, tout_);
            xp[q] = pk(fmaxf(v0, 0.01f * v0), fmaxf(v1, 0.01f * v1));
        }
    }

    // ---- fc1 -> mu (=z), fc2 -> logvar (constant port) ----
    u64 zp[8];
#pragma unroll
    for (int q = 0; q < 8; q++) {
        float z0 = cF1b[2*q]     + dot16c(cF1 + (2*q)*16,   xp);
        float z1 = cF1b[2*q + 1] + dot16c(cF1 + (2*q+1)*16, xp);
        zp[q] = pk(z0, z1);
    }
    if (n < 13) {
        ulonglong2* o = (ulonglong2*)(out + muOff + ((size_t)(b0 + sub) * 13 + n) * 16);
#pragma unroll
        for (int q = 0; q < 4; q++) {
            ulonglong2 v; v.x = zp[2*q]; v.y = zp[2*q+1];
            o[q] = v;
        }
        ulonglong2* o2 = (ulonglong2*)(out + lvOff + ((size_t)(b0 + sub) * 13 + n) * 16);
#pragma unroll
        for (int q = 0; q < 4; q++) {
            ulonglong2 v;
            v.x = pk(cF2b[4*q]   + dot16c(cF2 + (4*q)*16,   xp),
                     cF2b[4*q+1] + dot16c(cF2 + (4*q+1)*16, xp));
            v.y = pk(cF2b[4*q+2] + dot16c(cF2 + (4*q+2)*16, xp),
                     cF2b[4*q+3] + dot16c(cF2 + (4*q+3)*16, xp));
            o2[q] = v;
        }
    }

    // ---- decoder: per channel k, recon = relu(T T^T); adjT dead, scw = rb ----
    float* rb = scw;
    for (int k = 0; k < 4; k++) {
        u64 tp2[8];
#pragma unroll
        for (int q = 0; q < 8; q++) {
            float t0 = cDB[k*16 + 2*q]     + dot16s(sDW + k*256 + (2*q)*16,   zp);
            float t1 = cDB[k*16 + 2*q + 1] + dot16s(sDW + k*256 + (2*q+1)*16, zp);
            tp2[q] = pk(t0, t1);
        }

        __syncwarp();      // prior readers of xb done
        if (n < 13) {
            ulonglong2* tv = (ulonglong2*)(xb + (sub * 13 + nn) * 16);
#pragma unroll
            for (int q = 0; q < 4; q++) {
                ulonglong2 v; v.x = tp2[2*q]; v.y = tp2[2*q+1];
                tv[q] = v;
            }
        }
        __syncwarp();

        float r[13];
#pragma unroll
        for (int m = 0; m < 13; m++) {
            const ulonglong2* tv = (const ulonglong2*)(xb + (sub * 13 + m) * 16);
            ulonglong2 v0 = tv[0], v1 = tv[1], v2 = tv[2], v3 = tv[3];
            u64 s0 = mul2(tp2[0], v0.x);
            u64 s1 = mul2(tp2[1], v0.y);
            s0 = fma2(tp2[2], v1.x, s0);
            s1 = fma2(tp2[3], v1.y, s1);
            s0 = fma2(tp2[4], v2.x, s0);
            s1 = fma2(tp2[5], v2.y, s1);
            s0 = fma2(tp2[6], v3.x, s0);
            s1 = fma2(tp2[7], v3.y, s1);
            s0 = add2(s0, s1);
            float x0, x1; upk(s0, x0, x1);
            r[m] = fmaxf(x0 + x1, 0.0f);
        }
        if (n < 13) {
#pragma unroll
            for (int m = 0; m < 13; m++) rb[sub * 169 + nn * 13 + m] = r[m];
        }
        __syncwarp();
        for (int t = lane; t < 338; t += 32) {
            int s2 = (t >= 169) ? 1 : 0;
            int rr = t - 169 * s2;
            out[((size_t)(b0 + s2) * 4 + k) * 169 + rr] = rb[t];
        }
        __syncwarp();
    }
}

extern "C" void kernel_launch(void* const* d_in, const int* in_sizes, int n_in,
                              void* d_out, int out_size) {
    cudaMemcpyToSymbolAsync(cWi,  d_in[1],  208 * 4, 0, cudaMemcpyDeviceToDevice);
    cudaMemcpyToSymbolAsync(cEps, d_in[2],    4 * 4, 0, cudaMemcpyDeviceToDevice);
    cudaMemcpyToSymbolAsync(cB0,  d_in[4],   64 * 4, 0, cudaMemcpyDeviceToDevice);
    cudaMemcpyToSymbolAsync(cB1,  d_in[6],   64 * 4, 0, cudaMemcpyDeviceToDevice);
    cudaMemcpyToSymbolAsync(cF1,  d_in[15], 256 * 4, 0, cudaMemcpyDeviceToDevice);
    cudaMemcpyToSymbolAsync(cF1b, d_in[16],  16 * 4, 0, cudaMemcpyDeviceToDevice);
    cudaMemcpyToSymbolAsync(cF2,  d_in[17], 256 * 4, 0, cudaMemcpyDeviceToDevice);
    cudaMemcpyToSymbolAsync(cF2b, d_in[18],  16 * 4, 0, cudaMemcpyDeviceToDevice);
    cudaMemcpyToSymbolAsync(cDB,  d_in[20],  64 * 4, 0, cudaMemcpyDeviceToDevice);

    const float* adj = (const float*)d_in[0];
    float* out = (float*)d_out;
    int B = in_sizes[0] / 676;
    int grid = (B + 7) / 8;
    gvae_kernel<<<grid, 128>>>(adj,
        (const float*)d_in[3],  (const float*)d_in[5],  (const float*)d_in[19],
        (const float*)d_in[7],  (const float*)d_in[8],
        (const float*)d_in[9],  (const float*)d_in[10],
        (const float*)d_in[11], (const float*)d_in[12],
        (const float*)d_in[13], (const float*)d_in[14],
        out, B);
}